// round 13
// baseline (speedup 1.0000x reference)
#include <cuda_runtime.h>
#include <cuda_fp16.h>

#define NN 100000
#define NE 1600000
#define FIN 128
#define FH  64
#define FO  10

#define SCAN_BLK 512
#define NSCAN ((NN + SCAN_BLK - 1) / SCAN_BLK)   // 196

typedef unsigned long long u64;

// ---- scratch (device globals; no allocation allowed) ----
__device__ int   g_indeg[NN];
__device__ int   g_off[NN];
__device__ int   g_cursor[NN];
__device__ int   g_offp[NN];
__device__ int   g_bsum[NSCAN];
__device__ int   g_csrc[NE];
__device__ float g_dinv[NN];
__device__ __align__(16) __half g_hs[NN * FH];    // x@W1 (unscaled, then *= dinv)
__device__ __align__(16) __half g_aggh[NN * FH];  // fp16 relu(b1+dinv*(...)), 128B rows
__device__ __align__(16) __half g_h2s[NN * 16];   // (agg@W2)*dinv, fp16, stride 16

// ---- packed f32x2 helpers ----
__device__ __forceinline__ u64 dup2(float v) {
    u64 d; asm("mov.b64 %0, {%1,%1};" : "=l"(d) : "f"(v)); return d;
}
__device__ __forceinline__ void ffma2(u64& d, u64 a, u64 b) {
    asm("fma.rn.f32x2 %0, %1, %2, %0;" : "+l"(d) : "l"(a), "l"(b));
}
__device__ __forceinline__ float2 unpack2(u64 d) {
    float lo, hi; asm("mov.b64 {%0,%1}, %2;" : "=f"(lo), "=f"(hi) : "l"(d));
    return make_float2(lo, hi);
}
__device__ __forceinline__ unsigned h2_bits(__half2 h) {
    return *reinterpret_cast<unsigned*>(&h);
}

// ================= degree =================
__global__ void k_indeg(const int* __restrict__ dst) {
    int e = blockIdx.x * blockDim.x + threadIdx.x;
    if (e < NE) atomicAdd(&g_indeg[dst[e]], 1);
}

// ================= scan pass 1 (+ dinv fused) =================
__global__ void __launch_bounds__(SCAN_BLK) k_scan1() {
    int i = blockIdx.x * SCAN_BLK + threadIdx.x;
    int v = (i < NN) ? g_indeg[i] : 0;
    if (i < NN) g_dinv[i] = rsqrtf(1.0f + (float)v);
    int lane = threadIdx.x & 31, w = threadIdx.x >> 5;
    int s = v;
#pragma unroll
    for (int o = 1; o < 32; o <<= 1) {
        int t = __shfl_up_sync(0xffffffffu, s, o);
        if (lane >= o) s += t;
    }
    __shared__ int wsum[16];
    if (lane == 31) wsum[w] = s;
    __syncthreads();
    if (w == 0) {
        int t = (lane < 16) ? wsum[lane] : 0;
#pragma unroll
        for (int o = 1; o < 16; o <<= 1) {
            int u = __shfl_up_sync(0xffffffffu, t, o);
            if (lane >= o) t += u;
        }
        if (lane < 16) wsum[lane] = t;
    }
    __syncthreads();
    int excl = s - v + ((w > 0) ? wsum[w - 1] : 0);
    if (i < NN) g_offp[i] = excl;
    if (threadIdx.x == 0) g_bsum[blockIdx.x] = wsum[15];
}

// ===== scan pass 2 fused into apply: every block scans the 196 block sums =====
__global__ void __launch_bounds__(256) k_scan_apply() {
    __shared__ int s_ex[256];
    int tid = threadIdx.x;
    {
        int v = (tid < NSCAN) ? g_bsum[tid] : 0;
        int lane = tid & 31, w = tid >> 5;
        int s = v;
#pragma unroll
        for (int o = 1; o < 32; o <<= 1) {
            int t = __shfl_up_sync(0xffffffffu, s, o);
            if (lane >= o) s += t;
        }
        __shared__ int wsum[8];
        if (lane == 31) wsum[w] = s;
        __syncthreads();
        if (w == 0) {
            int t = (lane < 8) ? wsum[lane] : 0;
#pragma unroll
            for (int o = 1; o < 8; o <<= 1) {
                int u = __shfl_up_sync(0xffffffffu, t, o);
                if (lane >= o) t += u;
            }
            if (lane < 8) wsum[lane] = t;
        }
        __syncthreads();
        s_ex[tid] = s - v + ((w > 0) ? wsum[w - 1] : 0);  // exclusive
        __syncthreads();
    }
    int i = blockIdx.x * 256 + tid;
    if (i < NN) {
        int o = g_offp[i] + s_ex[i >> 9];
        g_off[i] = o;
        g_cursor[i] = o;
    }
}

// ================= CSR positional scatter =================
__global__ void k_edge_pos(const int* __restrict__ src, const int* __restrict__ dst) {
    int e = blockIdx.x * blockDim.x + threadIdx.x;
    if (e < NE) {
        int pos = atomicAdd(&g_cursor[dst[e]], 1);
        g_csrc[pos] = src[e];
    }
}

// ================= GEMM1: hs = half(x @ W1)  (unscaled; no deps) =============
#define XS_F4 (256 * 17)
#define GEMM1_SMEM (XS_F4 * 16 + 64 * 64 * 4)   // 86016 B

__global__ void __launch_bounds__(256, 2) k_gemm1(const float* __restrict__ x,
                                                  const float* __restrict__ W1) {
    extern __shared__ float4 sm4[];
    float4* xs4 = sm4;                     // [256][17]
    float*  Ws  = (float*)(sm4 + XS_F4);   // [64][64]

    const int tid = threadIdx.x;
    const int c  = tid & 7;
    const int rg = tid >> 3;
    const int row_base = blockIdx.x * 256;

    u64 acc[8][4];
#pragma unroll
    for (int i = 0; i < 8; i++)
#pragma unroll
        for (int p = 0; p < 4; p++) acc[i][p] = 0ull;

    const float4* x4  = reinterpret_cast<const float4*>(x);
    const float4* W14 = reinterpret_cast<const float4*>(W1);
    float4* Ws4 = reinterpret_cast<float4*>(Ws);

    for (int kc = 0; kc < 2; kc++) {
#pragma unroll
        for (int j = 0; j < 16; j++) {
            int f = tid + 256 * j;
            int row = f >> 4;
            int kq  = f & 15;
            int grow = min(row_base + row, NN - 1);
            xs4[row * 17 + kq] = x4[(size_t)grow * 32 + kc * 16 + kq];
        }
#pragma unroll
        for (int j = 0; j < 4; j++) {
            int f = tid + 256 * j;
            Ws4[f] = W14[kc * 1024 + f];
        }
        __syncthreads();

#define ROWSTEP(i, comp)                                   \
        {                                                  \
            u64 xd = dup2(xq[i].comp);                     \
            ffma2(acc[i][0], xd, wA.x);                    \
            ffma2(acc[i][1], xd, wA.y);                    \
            ffma2(acc[i][2], xd, wB.x);                    \
            ffma2(acc[i][3], xd, wB.y);                    \
        }
#define KSTEP(comp, kk)                                                        \
        {                                                                      \
            const ulonglong2* wr =                                             \
                (const ulonglong2*)(Ws + (k4 * 4 + kk) * 64 + c * 8);          \
            ulonglong2 wA = wr[0];                                             \
            ulonglong2 wB = wr[1];                                             \
            ROWSTEP(0, comp) ROWSTEP(1, comp) ROWSTEP(2, comp) ROWSTEP(3, comp)\
            ROWSTEP(4, comp) ROWSTEP(5, comp) ROWSTEP(6, comp) ROWSTEP(7, comp)\
        }

#pragma unroll 4
        for (int k4 = 0; k4 < 16; k4++) {
            float4 xq[8];
#pragma unroll
            for (int i = 0; i < 8; i++) xq[i] = xs4[(rg + 32 * i) * 17 + k4];
            KSTEP(x, 0)
            KSTEP(y, 1)
            KSTEP(z, 2)
            KSTEP(w, 3)
        }
        __syncthreads();
    }

    uint4* hs16 = reinterpret_cast<uint4*>(g_hs);
#pragma unroll
    for (int i = 0; i < 8; i++) {
        int grow = row_base + rg + 32 * i;
        if (grow < NN) {
            float2 p0 = unpack2(acc[i][0]);
            float2 p1 = unpack2(acc[i][1]);
            float2 p2 = unpack2(acc[i][2]);
            float2 p3 = unpack2(acc[i][3]);
            uint4 u;
            u.x = h2_bits(__float22half2_rn(p0));
            u.y = h2_bits(__float22half2_rn(p1));
            u.z = h2_bits(__float22half2_rn(p2));
            u.w = h2_bits(__float22half2_rn(p3));
            hs16[(size_t)grow * 8 + c] = u;
        }
    }
#undef KSTEP
#undef ROWSTEP
}

// ================= scale: hs[n][:] *= dinv[n]  (on s2, overlapped) ===========
__global__ void __launch_bounds__(256) k_scale() {
    int idx = blockIdx.x * blockDim.x + threadIdx.x;  // over NN*8 uint4
    if (idx >= NN * 8) return;
    int n = idx >> 3;
    float di = g_dinv[n];
    uint4* hs16 = reinterpret_cast<uint4*>(g_hs);
    uint4 u = hs16[idx];
    unsigned* up = &u.x;
#pragma unroll
    for (int p = 0; p < 4; p++) {
        __half2 h = *reinterpret_cast<__half2*>(&up[p]);
        float2 f = __half22float2(h);
        f.x *= di; f.y *= di;
        up[p] = h2_bits(__float22half2_rn(f));
    }
    hs16[idx] = u;
}

// ===== agg1: warp-per-node, 4-edge fp16 tree per step =====
__global__ void __launch_bounds__(256) k_agg1(const float* __restrict__ b1) {
    int wg = (blockIdx.x * blockDim.x + threadIdx.x) >> 5;
    if (wg >= NN) return;
    const int d = wg;
    const int lane = threadIdx.x & 31;
    const int g  = lane >> 3;   // edge group 0..3
    const int fl = lane & 7;    // feature chunk: halves [fl*8, fl*8+8)

    const uint4* hs4 = reinterpret_cast<const uint4*>(g_hs);  // row = 8 uint4

    float facc[8];
#pragma unroll
    for (int p = 0; p < 8; p++) facc[p] = 0.0f;

    const int beg = g_off[d];
    const int cnt = g_indeg[d];
    const uint4 zero4 = make_uint4(0u, 0u, 0u, 0u);
    for (int base = 0; base < cnt; base += 32) {
        int rem = cnt - base;
        int take = rem < 32 ? rem : 32;
        int s = 0;
        if (lane < take) s = g_csrc[beg + base + lane];
#pragma unroll
        for (int q = 0; q < 32; q += 16) {
            int e0 = q + g;
            int e1 = q + 4 + g;
            int e2 = q + 8 + g;
            int e3 = q + 12 + g;
            int s0 = __shfl_sync(0xffffffffu, s, e0);
            int s1 = __shfl_sync(0xffffffffu, s, e1);
            int s2 = __shfl_sync(0xffffffffu, s, e2);
            int s3 = __shfl_sync(0xffffffffu, s, e3);
            if (e0 < take) {
                uint4 u0 = hs4[(size_t)s0 * 8 + fl];
                uint4 u1 = (e1 < take) ? hs4[(size_t)s1 * 8 + fl] : zero4;
                uint4 u2 = (e2 < take) ? hs4[(size_t)s2 * 8 + fl] : zero4;
                uint4 u3 = (e3 < take) ? hs4[(size_t)s3 * 8 + fl] : zero4;
                const __half2* h0 = reinterpret_cast<const __half2*>(&u0);
                const __half2* h1 = reinterpret_cast<const __half2*>(&u1);
                const __half2* h2 = reinterpret_cast<const __half2*>(&u2);
                const __half2* h3 = reinterpret_cast<const __half2*>(&u3);
#pragma unroll
                for (int p = 0; p < 4; p++) {
                    __half2 t = __hadd2(__hadd2(h0[p], h1[p]), __hadd2(h2[p], h3[p]));
                    float2 f = __half22float2(t);
                    facc[2 * p]     += f.x;
                    facc[2 * p + 1] += f.y;
                }
            }
        }
    }

    // reduce across the 4 edge groups
#pragma unroll
    for (int off = 8; off < 32; off <<= 1) {
#pragma unroll
        for (int p = 0; p < 8; p++)
            facc[p] += __shfl_xor_sync(0xffffffffu, facc[p], off);
    }

    if (g == 0) {
        uint4 u = hs4[(size_t)d * 8 + fl];
        const __half2* hp = reinterpret_cast<const __half2*>(&u);
#pragma unroll
        for (int p = 0; p < 4; p++) {
            float2 f = __half22float2(hp[p]);
            facc[2 * p]     += f.x;
            facc[2 * p + 1] += f.y;
        }
        float di = g_dinv[d];
        const float4* b4 = reinterpret_cast<const float4*>(b1);
        float4 bb0 = b4[fl * 2];
        float4 bb1 = b4[fl * 2 + 1];
        float o0 = fmaxf(fmaf(facc[0], di, bb0.x), 0.0f);
        float o1 = fmaxf(fmaf(facc[1], di, bb0.y), 0.0f);
        float o2 = fmaxf(fmaf(facc[2], di, bb0.z), 0.0f);
        float o3 = fmaxf(fmaf(facc[3], di, bb0.w), 0.0f);
        float o4 = fmaxf(fmaf(facc[4], di, bb1.x), 0.0f);
        float o5 = fmaxf(fmaf(facc[5], di, bb1.y), 0.0f);
        float o6 = fmaxf(fmaf(facc[6], di, bb1.z), 0.0f);
        float o7 = fmaxf(fmaf(facc[7], di, bb1.w), 0.0f);
        uint4 w;
        w.x = h2_bits(__float22half2_rn(make_float2(o0, o1)));
        w.y = h2_bits(__float22half2_rn(make_float2(o2, o3)));
        w.z = h2_bits(__float22half2_rn(make_float2(o4, o5)));
        w.w = h2_bits(__float22half2_rn(make_float2(o6, o7)));
        reinterpret_cast<uint4*>(g_aggh)[(size_t)d * 8 + fl] = w;
    }
}

// ========== GEMM2: h2s = half((aggh @ W2) * dinv[row]), fp16 inputs ==========
__global__ void __launch_bounds__(256) k_gemm2(const float* __restrict__ W2) {
    __shared__ float Ws[FH * FO];
    for (int i = threadIdx.x; i < FH * FO; i += blockDim.x) Ws[i] = W2[i];
    __syncthreads();

    int n = blockIdx.x * blockDim.x + threadIdx.x;
    if (n >= NN) return;

    float acc[FO];
#pragma unroll
    for (int j = 0; j < FO; j++) acc[j] = 0.0f;

    const uint4* a4 = reinterpret_cast<const uint4*>(g_aggh) + (size_t)n * 8;
#pragma unroll
    for (int k4 = 0; k4 < 8; k4++) {
        uint4 u = a4[k4];
        const __half2* hp = reinterpret_cast<const __half2*>(&u);
#pragma unroll
        for (int pp = 0; pp < 4; pp++) {
            float2 f = __half22float2(hp[pp]);
            int k = k4 * 8 + pp * 2;
#pragma unroll
            for (int j = 0; j < FO; j++) acc[j] = fmaf(f.x, Ws[k * FO + j], acc[j]);
#pragma unroll
            for (int j = 0; j < FO; j++) acc[j] = fmaf(f.y, Ws[(k + 1) * FO + j], acc[j]);
        }
    }

    float di = g_dinv[n];
    unsigned* o2 = reinterpret_cast<unsigned*>(g_h2s + (size_t)n * 16);
#pragma unroll
    for (int p = 0; p < 5; p++) {
        __half2 h = __float22half2_rn(make_float2(acc[p * 2] * di, acc[p * 2 + 1] * di));
        o2[p] = h2_bits(h);
    }
}

// ===== agg2: warp-per-node, 4-edge fp16 tree per step =====
__global__ void __launch_bounds__(256) k_agg2(const float* __restrict__ b2,
                                              float* __restrict__ out) {
    int wg = (blockIdx.x * blockDim.x + threadIdx.x) >> 5;
    if (wg >= NN) return;
    const int d = wg;
    const int lane = threadIdx.x & 31;
    const int g  = lane >> 3;
    const int fl = lane & 7;

    const __half2* h2p = reinterpret_cast<const __half2*>(g_h2s);  // row = 8 half2

    float2 acc = make_float2(0.f, 0.f);
    const __half2 hz = __float2half2_rn(0.0f);

    const int beg = g_off[d];
    const int cnt = g_indeg[d];
    for (int base = 0; base < cnt; base += 32) {
        int rem = cnt - base;
        int take = rem < 32 ? rem : 32;
        int s = 0;
        if (lane < take) s = g_csrc[beg + base + lane];
#pragma unroll
        for (int q = 0; q < 32; q += 16) {
            int e0 = q + g;
            int e1 = q + 4 + g;
            int e2 = q + 8 + g;
            int e3 = q + 12 + g;
            int s0 = __shfl_sync(0xffffffffu, s, e0);
            int s1 = __shfl_sync(0xffffffffu, s, e1);
            int s2 = __shfl_sync(0xffffffffu, s, e2);
            int s3 = __shfl_sync(0xffffffffu, s, e3);
            if (e0 < take && fl < 5) {
                __half2 v0 = h2p[(size_t)s0 * 8 + fl];
                __half2 v1 = (e1 < take) ? h2p[(size_t)s1 * 8 + fl] : hz;
                __half2 v2 = (e2 < take) ? h2p[(size_t)s2 * 8 + fl] : hz;
                __half2 v3 = (e3 < take) ? h2p[(size_t)s3 * 8 + fl] : hz;
                float2 f = __half22float2(__hadd2(__hadd2(v0, v1), __hadd2(v2, v3)));
                acc.x += f.x;
                acc.y += f.y;
            }
        }
    }

    // reduce across the 4 edge groups
#pragma unroll
    for (int off = 8; off < 32; off <<= 1) {
        acc.x += __shfl_xor_sync(0xffffffffu, acc.x, off);
        acc.y += __shfl_xor_sync(0xffffffffu, acc.y, off);
    }

    if (g == 0 && fl < 5) {
        float2 self = __half22float2(h2p[(size_t)d * 8 + fl]);
        acc.x += self.x;
        acc.y += self.y;
        float di = g_dinv[d];
        float* op = out + (size_t)d * FO;
        op[fl * 2]     = fmaf(acc.x, di, b2[fl * 2]);
        op[fl * 2 + 1] = fmaf(acc.y, di, b2[fl * 2 + 1]);
    }
}

extern "C" void kernel_launch(void* const* d_in, const int* in_sizes, int n_in,
                              void* d_out, int out_size) {
    const float* x  = (const float*)d_in[0];
    const int*   ei = (const int*)d_in[1];
    const float* W1 = (const float*)d_in[2];
    const float* b1 = (const float*)d_in[3];
    const float* W2 = (const float*)d_in[4];
    const float* b2 = (const float*)d_in[5];
    float* out = (float*)d_out;

    const int* src = ei;
    const int* dst = ei + NE;

    static bool init_done = false;
    static cudaStream_t s2;
    static cudaEvent_t ev_fork, ev_scan1, ev_join;
    static void* indeg_ptr = nullptr;
    if (!init_done) {
        cudaFuncSetAttribute(k_gemm1, cudaFuncAttributeMaxDynamicSharedMemorySize,
                             GEMM1_SMEM);
        cudaStreamCreateWithFlags(&s2, cudaStreamNonBlocking);
        cudaEventCreateWithFlags(&ev_fork, cudaEventDisableTiming);
        cudaEventCreateWithFlags(&ev_scan1, cudaEventDisableTiming);
        cudaEventCreateWithFlags(&ev_join, cudaEventDisableTiming);
        cudaGetSymbolAddress(&indeg_ptr, g_indeg);
        init_done = true;
    }

    // ---- fork immediately: gemm1 has no input deps ----
    cudaEventRecord(ev_fork, 0);
    cudaStreamWaitEvent(s2, ev_fork, 0);
    k_gemm1<<<(NN + 255) / 256, 256, GEMM1_SMEM, s2>>>(x, W1);

    // ---- prepass on capture stream, concurrent with gemm1 ----
    cudaMemsetAsync(indeg_ptr, 0, NN * sizeof(int), 0);
    k_indeg<<<(NE + 255) / 256, 256>>>(dst);
    k_scan1<<<NSCAN, SCAN_BLK>>>();
    cudaEventRecord(ev_scan1, 0);

    // s2: scale hs as soon as gemm1 + scan1 are both done (overlaps edge_pos)
    cudaStreamWaitEvent(s2, ev_scan1, 0);
    k_scale<<<(NN * 8 + 255) / 256, 256, 0, s2>>>();

    k_scan_apply<<<(NN + 255) / 256, 256>>>();
    k_edge_pos<<<(NE + 255) / 256, 256>>>(src, dst);

    // ---- join ----
    cudaEventRecord(ev_join, s2);
    cudaStreamWaitEvent(0, ev_join, 0);

    k_agg1<<<(NN * 32 + 255) / 256, 256>>>(b1);
    k_gemm2<<<(NN + 255) / 256, 256>>>(W2);
    k_agg2<<<(NN * 32 + 255) / 256, 256>>>(b2, out);
}

// round 14
// speedup vs baseline: 1.0526x; 1.0526x over previous
#include <cuda_runtime.h>
#include <cuda_fp16.h>

#define NN 100000
#define NE 1600000
#define FIN 128
#define FH  64
#define FO  10

#define SCAN_BLK 512
#define NSCAN ((NN + SCAN_BLK - 1) / SCAN_BLK)   // 196

typedef unsigned long long u64;

// ---- scratch (device globals; no allocation allowed) ----
__device__ int   g_indeg[NN];
__device__ int   g_off[NN];
__device__ int   g_cursor[NN];
__device__ int   g_offp[NN];
__device__ int   g_bsum[NSCAN];
__device__ int   g_csrc[NE];
__device__ float g_dinv[NN];
__device__ __align__(16) __half g_hs[NN * FH];    // x@W1 (unscaled, then *= dinv)
__device__ __align__(16) __half g_aggh[NN * FH];  // fp16 relu(b1+dinv*(...)), 128B rows
__device__ __align__(16) __half g_h2s[NN * 16];   // (agg@W2)*dinv, fp16, stride 16

// ---- packed f32x2 helpers ----
__device__ __forceinline__ u64 dup2(float v) {
    u64 d; asm("mov.b64 %0, {%1,%1};" : "=l"(d) : "f"(v)); return d;
}
__device__ __forceinline__ void ffma2(u64& d, u64 a, u64 b) {
    asm("fma.rn.f32x2 %0, %1, %2, %0;" : "+l"(d) : "l"(a), "l"(b));
}
__device__ __forceinline__ float2 unpack2(u64 d) {
    float lo, hi; asm("mov.b64 {%0,%1}, %2;" : "=f"(lo), "=f"(hi) : "l"(d));
    return make_float2(lo, hi);
}
__device__ __forceinline__ unsigned h2_bits(__half2 h) {
    return *reinterpret_cast<unsigned*>(&h);
}

// ================= degree =================
__global__ void k_indeg(const int* __restrict__ dst) {
    int e = blockIdx.x * blockDim.x + threadIdx.x;
    if (e < NE) atomicAdd(&g_indeg[dst[e]], 1);
}

// ================= scan pass 1 (+ dinv fused) =================
__global__ void __launch_bounds__(SCAN_BLK) k_scan1() {
    int i = blockIdx.x * SCAN_BLK + threadIdx.x;
    int v = (i < NN) ? g_indeg[i] : 0;
    if (i < NN) g_dinv[i] = rsqrtf(1.0f + (float)v);
    int lane = threadIdx.x & 31, w = threadIdx.x >> 5;
    int s = v;
#pragma unroll
    for (int o = 1; o < 32; o <<= 1) {
        int t = __shfl_up_sync(0xffffffffu, s, o);
        if (lane >= o) s += t;
    }
    __shared__ int wsum[16];
    if (lane == 31) wsum[w] = s;
    __syncthreads();
    if (w == 0) {
        int t = (lane < 16) ? wsum[lane] : 0;
#pragma unroll
        for (int o = 1; o < 16; o <<= 1) {
            int u = __shfl_up_sync(0xffffffffu, t, o);
            if (lane >= o) t += u;
        }
        if (lane < 16) wsum[lane] = t;
    }
    __syncthreads();
    int excl = s - v + ((w > 0) ? wsum[w - 1] : 0);
    if (i < NN) g_offp[i] = excl;
    if (threadIdx.x == 0) g_bsum[blockIdx.x] = wsum[15];
}

// ===== scan pass 2 fused into apply: every block scans the 196 block sums =====
__global__ void __launch_bounds__(256) k_scan_apply() {
    __shared__ int s_ex[256];
    int tid = threadIdx.x;
    {
        int v = (tid < NSCAN) ? g_bsum[tid] : 0;
        int lane = tid & 31, w = tid >> 5;
        int s = v;
#pragma unroll
        for (int o = 1; o < 32; o <<= 1) {
            int t = __shfl_up_sync(0xffffffffu, s, o);
            if (lane >= o) s += t;
        }
        __shared__ int wsum[8];
        if (lane == 31) wsum[w] = s;
        __syncthreads();
        if (w == 0) {
            int t = (lane < 8) ? wsum[lane] : 0;
#pragma unroll
            for (int o = 1; o < 8; o <<= 1) {
                int u = __shfl_up_sync(0xffffffffu, t, o);
                if (lane >= o) t += u;
            }
            if (lane < 8) wsum[lane] = t;
        }
        __syncthreads();
        s_ex[tid] = s - v + ((w > 0) ? wsum[w - 1] : 0);  // exclusive
        __syncthreads();
    }
    int i = blockIdx.x * 256 + tid;
    if (i < NN) {
        int o = g_offp[i] + s_ex[i >> 9];
        g_off[i] = o;
        g_cursor[i] = o;
    }
}

// ================= CSR positional scatter =================
__global__ void k_edge_pos(const int* __restrict__ src, const int* __restrict__ dst) {
    int e = blockIdx.x * blockDim.x + threadIdx.x;
    if (e < NE) {
        int pos = atomicAdd(&g_cursor[dst[e]], 1);
        g_csrc[pos] = src[e];
    }
}

// ================= GEMM1: hs = half(x @ W1)  (unscaled; no deps) =============
#define XS_F4 (256 * 17)
#define GEMM1_SMEM (XS_F4 * 16 + 64 * 64 * 4)   // 86016 B

__global__ void __launch_bounds__(256, 2) k_gemm1(const float* __restrict__ x,
                                                  const float* __restrict__ W1) {
    extern __shared__ float4 sm4[];
    float4* xs4 = sm4;                     // [256][17]
    float*  Ws  = (float*)(sm4 + XS_F4);   // [64][64]

    const int tid = threadIdx.x;
    const int c  = tid & 7;
    const int rg = tid >> 3;
    const int row_base = blockIdx.x * 256;

    u64 acc[8][4];
#pragma unroll
    for (int i = 0; i < 8; i++)
#pragma unroll
        for (int p = 0; p < 4; p++) acc[i][p] = 0ull;

    const float4* x4  = reinterpret_cast<const float4*>(x);
    const float4* W14 = reinterpret_cast<const float4*>(W1);
    float4* Ws4 = reinterpret_cast<float4*>(Ws);

    for (int kc = 0; kc < 2; kc++) {
#pragma unroll
        for (int j = 0; j < 16; j++) {
            int f = tid + 256 * j;
            int row = f >> 4;
            int kq  = f & 15;
            int grow = min(row_base + row, NN - 1);
            xs4[row * 17 + kq] = x4[(size_t)grow * 32 + kc * 16 + kq];
        }
#pragma unroll
        for (int j = 0; j < 4; j++) {
            int f = tid + 256 * j;
            Ws4[f] = W14[kc * 1024 + f];
        }
        __syncthreads();

#define ROWSTEP(i, comp)                                   \
        {                                                  \
            u64 xd = dup2(xq[i].comp);                     \
            ffma2(acc[i][0], xd, wA.x);                    \
            ffma2(acc[i][1], xd, wA.y);                    \
            ffma2(acc[i][2], xd, wB.x);                    \
            ffma2(acc[i][3], xd, wB.y);                    \
        }
#define KSTEP(comp, kk)                                                        \
        {                                                                      \
            const ulonglong2* wr =                                             \
                (const ulonglong2*)(Ws + (k4 * 4 + kk) * 64 + c * 8);          \
            ulonglong2 wA = wr[0];                                             \
            ulonglong2 wB = wr[1];                                             \
            ROWSTEP(0, comp) ROWSTEP(1, comp) ROWSTEP(2, comp) ROWSTEP(3, comp)\
            ROWSTEP(4, comp) ROWSTEP(5, comp) ROWSTEP(6, comp) ROWSTEP(7, comp)\
        }

#pragma unroll 4
        for (int k4 = 0; k4 < 16; k4++) {
            float4 xq[8];
#pragma unroll
            for (int i = 0; i < 8; i++) xq[i] = xs4[(rg + 32 * i) * 17 + k4];
            KSTEP(x, 0)
            KSTEP(y, 1)
            KSTEP(z, 2)
            KSTEP(w, 3)
        }
        __syncthreads();
    }

    uint4* hs16 = reinterpret_cast<uint4*>(g_hs);
#pragma unroll
    for (int i = 0; i < 8; i++) {
        int grow = row_base + rg + 32 * i;
        if (grow < NN) {
            float2 p0 = unpack2(acc[i][0]);
            float2 p1 = unpack2(acc[i][1]);
            float2 p2 = unpack2(acc[i][2]);
            float2 p3 = unpack2(acc[i][3]);
            uint4 u;
            u.x = h2_bits(__float22half2_rn(p0));
            u.y = h2_bits(__float22half2_rn(p1));
            u.z = h2_bits(__float22half2_rn(p2));
            u.w = h2_bits(__float22half2_rn(p3));
            hs16[(size_t)grow * 8 + c] = u;
        }
    }
#undef KSTEP
#undef ROWSTEP
}

// ================= scale: hs[n][:] *= dinv[n]  (on s2, overlapped) ===========
__global__ void __launch_bounds__(256) k_scale() {
    int idx = blockIdx.x * blockDim.x + threadIdx.x;  // over NN*8 uint4
    if (idx >= NN * 8) return;
    int n = idx >> 3;
    float di = g_dinv[n];
    uint4* hs16 = reinterpret_cast<uint4*>(g_hs);
    uint4 u = hs16[idx];
    unsigned* up = &u.x;
#pragma unroll
    for (int p = 0; p < 4; p++) {
        __half2 h = *reinterpret_cast<__half2*>(&up[p]);
        float2 f = __half22float2(h);
        f.x *= di; f.y *= di;
        up[p] = h2_bits(__float22half2_rn(f));
    }
    hs16[idx] = u;
}

// ===== agg1: warp-per-node, 2x4 edges/iteration, pairwise HADD2 (R12 form) =====
__global__ void __launch_bounds__(256) k_agg1(const float* __restrict__ b1) {
    int wg = (blockIdx.x * blockDim.x + threadIdx.x) >> 5;
    if (wg >= NN) return;
    const int d = wg;
    const int lane = threadIdx.x & 31;
    const int g  = lane >> 3;   // edge group 0..3
    const int fl = lane & 7;    // feature chunk: halves [fl*8, fl*8+8)

    const uint4* hs4 = reinterpret_cast<const uint4*>(g_hs);  // row = 8 uint4

    float facc[8];
#pragma unroll
    for (int p = 0; p < 8; p++) facc[p] = 0.0f;

    const int beg = g_off[d];
    const int cnt = g_indeg[d];
    for (int base = 0; base < cnt; base += 32) {
        int rem = cnt - base;
        int take = rem < 32 ? rem : 32;
        int s = 0;
        if (lane < take) s = __ldg(&g_csrc[beg + base + lane]);
#pragma unroll
        for (int q = 0; q < 32; q += 8) {
            int e0 = q + g;
            int e1 = q + 4 + g;
            int s0 = __shfl_sync(0xffffffffu, s, e0);
            int s1 = __shfl_sync(0xffffffffu, s, e1);
            if (e0 < take) {
                uint4 u0 = __ldg(&hs4[(size_t)s0 * 8 + fl]);
                uint4 u1 = make_uint4(0u, 0u, 0u, 0u);
                if (e1 < take) u1 = __ldg(&hs4[(size_t)s1 * 8 + fl]);
                const __half2* h0 = reinterpret_cast<const __half2*>(&u0);
                const __half2* h1 = reinterpret_cast<const __half2*>(&u1);
#pragma unroll
                for (int p = 0; p < 4; p++) {
                    __half2 hsum = __hadd2(h0[p], h1[p]);
                    float2 f = __half22float2(hsum);
                    facc[2 * p]     += f.x;
                    facc[2 * p + 1] += f.y;
                }
            }
        }
    }

    // reduce across the 4 edge groups
#pragma unroll
    for (int off = 8; off < 32; off <<= 1) {
#pragma unroll
        for (int p = 0; p < 8; p++)
            facc[p] += __shfl_xor_sync(0xffffffffu, facc[p], off);
    }

    if (g == 0) {
        uint4 u = __ldg(&hs4[(size_t)d * 8 + fl]);
        const __half2* hp = reinterpret_cast<const __half2*>(&u);
#pragma unroll
        for (int p = 0; p < 4; p++) {
            float2 f = __half22float2(hp[p]);
            facc[2 * p]     += f.x;
            facc[2 * p + 1] += f.y;
        }
        float di = g_dinv[d];
        const float4* b4 = reinterpret_cast<const float4*>(b1);
        float4 bb0 = b4[fl * 2];
        float4 bb1 = b4[fl * 2 + 1];
        float o0 = fmaxf(fmaf(facc[0], di, bb0.x), 0.0f);
        float o1 = fmaxf(fmaf(facc[1], di, bb0.y), 0.0f);
        float o2 = fmaxf(fmaf(facc[2], di, bb0.z), 0.0f);
        float o3 = fmaxf(fmaf(facc[3], di, bb0.w), 0.0f);
        float o4 = fmaxf(fmaf(facc[4], di, bb1.x), 0.0f);
        float o5 = fmaxf(fmaf(facc[5], di, bb1.y), 0.0f);
        float o6 = fmaxf(fmaf(facc[6], di, bb1.z), 0.0f);
        float o7 = fmaxf(fmaf(facc[7], di, bb1.w), 0.0f);
        uint4 w;
        w.x = h2_bits(__float22half2_rn(make_float2(o0, o1)));
        w.y = h2_bits(__float22half2_rn(make_float2(o2, o3)));
        w.z = h2_bits(__float22half2_rn(make_float2(o4, o5)));
        w.w = h2_bits(__float22half2_rn(make_float2(o6, o7)));
        reinterpret_cast<uint4*>(g_aggh)[(size_t)d * 8 + fl] = w;
    }
}

// ========== GEMM2: h2s = half((aggh @ W2) * dinv[row]), fp16 inputs ==========
__global__ void __launch_bounds__(256) k_gemm2(const float* __restrict__ W2) {
    __shared__ float Ws[FH * FO];
    for (int i = threadIdx.x; i < FH * FO; i += blockDim.x) Ws[i] = W2[i];
    __syncthreads();

    int n = blockIdx.x * blockDim.x + threadIdx.x;
    if (n >= NN) return;

    float acc[FO];
#pragma unroll
    for (int j = 0; j < FO; j++) acc[j] = 0.0f;

    const uint4* a4 = reinterpret_cast<const uint4*>(g_aggh) + (size_t)n * 8;
#pragma unroll
    for (int k4 = 0; k4 < 8; k4++) {
        uint4 u = a4[k4];
        const __half2* hp = reinterpret_cast<const __half2*>(&u);
#pragma unroll
        for (int pp = 0; pp < 4; pp++) {
            float2 f = __half22float2(hp[pp]);
            int k = k4 * 8 + pp * 2;
#pragma unroll
            for (int j = 0; j < FO; j++) acc[j] = fmaf(f.x, Ws[k * FO + j], acc[j]);
#pragma unroll
            for (int j = 0; j < FO; j++) acc[j] = fmaf(f.y, Ws[(k + 1) * FO + j], acc[j]);
        }
    }

    float di = g_dinv[n];
    unsigned* o2 = reinterpret_cast<unsigned*>(g_h2s + (size_t)n * 16);
#pragma unroll
    for (int p = 0; p < 5; p++) {
        __half2 h = __float22half2_rn(make_float2(acc[p * 2] * di, acc[p * 2 + 1] * di));
        o2[p] = h2_bits(h);
    }
}

// ===== agg2: warp-per-node, 2x4 edges/iteration, pairwise HADD2 (R12 form) =====
__global__ void __launch_bounds__(256) k_agg2(const float* __restrict__ b2,
                                              float* __restrict__ out) {
    int wg = (blockIdx.x * blockDim.x + threadIdx.x) >> 5;
    if (wg >= NN) return;
    const int d = wg;
    const int lane = threadIdx.x & 31;
    const int g  = lane >> 3;
    const int fl = lane & 7;

    const __half2* h2p = reinterpret_cast<const __half2*>(g_h2s);  // row = 8 half2

    float2 acc = make_float2(0.f, 0.f);

    const int beg = g_off[d];
    const int cnt = g_indeg[d];
    for (int base = 0; base < cnt; base += 32) {
        int rem = cnt - base;
        int take = rem < 32 ? rem : 32;
        int s = 0;
        if (lane < take) s = __ldg(&g_csrc[beg + base + lane]);
#pragma unroll
        for (int q = 0; q < 32; q += 8) {
            int e0 = q + g;
            int e1 = q + 4 + g;
            int s0 = __shfl_sync(0xffffffffu, s, e0);
            int s1 = __shfl_sync(0xffffffffu, s, e1);
            if (e0 < take && fl < 5) {
                __half2 v0 = __ldg(&h2p[(size_t)s0 * 8 + fl]);
                __half2 v1 = __float2half2_rn(0.0f);
                if (e1 < take) v1 = __ldg(&h2p[(size_t)s1 * 8 + fl]);
                float2 f = __half22float2(__hadd2(v0, v1));
                acc.x += f.x;
                acc.y += f.y;
            }
        }
    }

    // reduce across the 4 edge groups
#pragma unroll
    for (int off = 8; off < 32; off <<= 1) {
        acc.x += __shfl_xor_sync(0xffffffffu, acc.x, off);
        acc.y += __shfl_xor_sync(0xffffffffu, acc.y, off);
    }

    if (g == 0 && fl < 5) {
        float2 self = __half22float2(__ldg(&h2p[(size_t)d * 8 + fl]));
        acc.x += self.x;
        acc.y += self.y;
        float di = g_dinv[d];
        float* op = out + (size_t)d * FO;
        op[fl * 2]     = fmaf(acc.x, di, b2[fl * 2]);
        op[fl * 2 + 1] = fmaf(acc.y, di, b2[fl * 2 + 1]);
    }
}

extern "C" void kernel_launch(void* const* d_in, const int* in_sizes, int n_in,
                              void* d_out, int out_size) {
    const float* x  = (const float*)d_in[0];
    const int*   ei = (const int*)d_in[1];
    const float* W1 = (const float*)d_in[2];
    const float* b1 = (const float*)d_in[3];
    const float* W2 = (const float*)d_in[4];
    const float* b2 = (const float*)d_in[5];
    float* out = (float*)d_out;

    const int* src = ei;
    const int* dst = ei + NE;

    static bool init_done = false;
    static cudaStream_t s2;
    static cudaEvent_t ev_fork, ev_scan1, ev_join;
    static void* indeg_ptr = nullptr;
    if (!init_done) {
        cudaFuncSetAttribute(k_gemm1, cudaFuncAttributeMaxDynamicSharedMemorySize,
                             GEMM1_SMEM);
        cudaStreamCreateWithFlags(&s2, cudaStreamNonBlocking);
        cudaEventCreateWithFlags(&ev_fork, cudaEventDisableTiming);
        cudaEventCreateWithFlags(&ev_scan1, cudaEventDisableTiming);
        cudaEventCreateWithFlags(&ev_join, cudaEventDisableTiming);
        cudaGetSymbolAddress(&indeg_ptr, g_indeg);
        init_done = true;
    }

    // ---- fork immediately: gemm1 has no input deps ----
    cudaEventRecord(ev_fork, 0);
    cudaStreamWaitEvent(s2, ev_fork, 0);
    k_gemm1<<<(NN + 255) / 256, 256, GEMM1_SMEM, s2>>>(x, W1);

    // ---- prepass on capture stream, concurrent with gemm1 ----
    cudaMemsetAsync(indeg_ptr, 0, NN * sizeof(int), 0);
    k_indeg<<<(NE + 255) / 256, 256>>>(dst);
    k_scan1<<<NSCAN, SCAN_BLK>>>();
    cudaEventRecord(ev_scan1, 0);

    // s2: scale hs as soon as gemm1 + scan1 are both done (overlaps edge_pos)
    cudaStreamWaitEvent(s2, ev_scan1, 0);
    k_scale<<<(NN * 8 + 255) / 256, 256, 0, s2>>>();

    k_scan_apply<<<(NN + 255) / 256, 256>>>();
    k_edge_pos<<<(NE + 255) / 256, 256>>>(src, dst);

    // ---- join ----
    cudaEventRecord(ev_join, s2);
    cudaStreamWaitEvent(0, ev_join, 0);

    k_agg1<<<(NN * 32 + 255) / 256, 256>>>(b1);
    k_gemm2<<<(NN + 255) / 256, 256>>>(W2);
    k_agg2<<<(NN * 32 + 255) / 256, 256>>>(b2, out);
}

// round 15
// speedup vs baseline: 1.1475x; 1.0901x over previous
#include <cuda_runtime.h>
#include <cuda_fp16.h>

#define NN 100000
#define NE 1600000
#define FIN 128
#define FH  64
#define FO  10

#define SCAN_BLK 512
#define NSCAN ((NN + SCAN_BLK - 1) / SCAN_BLK)   // 196

typedef unsigned long long u64;

// ---- scratch (device globals; no allocation allowed) ----
__device__ int   g_indeg[NN];
__device__ int   g_off[NN];
__device__ int   g_cursor[NN];
__device__ int   g_offp[NN];
__device__ int   g_bsum[NSCAN];
__device__ int   g_csrc[NE];
__device__ float g_dinv[NN];
__device__ __align__(16) __half g_hs[NN * FH];    // x@W1 (unscaled, then *= dinv)
__device__ __align__(16) __half g_aggh[NN * FH];  // fp16 relu(b1+dinv*(...)), 128B rows
__device__ __align__(16) __half g_h2s[NN * 16];   // (agg@W2)*dinv, fp16, stride 16

__device__ __forceinline__ unsigned h2_bits(__half2 h) {
    return *reinterpret_cast<unsigned*>(&h);
}

// ================= degree =================
__global__ void k_indeg(const int* __restrict__ dst) {
    int e = blockIdx.x * blockDim.x + threadIdx.x;
    if (e < NE) atomicAdd(&g_indeg[dst[e]], 1);
}

// ================= scan pass 1 (+ dinv fused) =================
__global__ void __launch_bounds__(SCAN_BLK) k_scan1() {
    int i = blockIdx.x * SCAN_BLK + threadIdx.x;
    int v = (i < NN) ? g_indeg[i] : 0;
    if (i < NN) g_dinv[i] = rsqrtf(1.0f + (float)v);
    int lane = threadIdx.x & 31, w = threadIdx.x >> 5;
    int s = v;
#pragma unroll
    for (int o = 1; o < 32; o <<= 1) {
        int t = __shfl_up_sync(0xffffffffu, s, o);
        if (lane >= o) s += t;
    }
    __shared__ int wsum[16];
    if (lane == 31) wsum[w] = s;
    __syncthreads();
    if (w == 0) {
        int t = (lane < 16) ? wsum[lane] : 0;
#pragma unroll
        for (int o = 1; o < 16; o <<= 1) {
            int u = __shfl_up_sync(0xffffffffu, t, o);
            if (lane >= o) t += u;
        }
        if (lane < 16) wsum[lane] = t;
    }
    __syncthreads();
    int excl = s - v + ((w > 0) ? wsum[w - 1] : 0);
    if (i < NN) g_offp[i] = excl;
    if (threadIdx.x == 0) g_bsum[blockIdx.x] = wsum[15];
}

// ===== scan pass 2 fused into apply =====
__global__ void __launch_bounds__(256) k_scan_apply() {
    __shared__ int s_ex[256];
    int tid = threadIdx.x;
    {
        int v = (tid < NSCAN) ? g_bsum[tid] : 0;
        int lane = tid & 31, w = tid >> 5;
        int s = v;
#pragma unroll
        for (int o = 1; o < 32; o <<= 1) {
            int t = __shfl_up_sync(0xffffffffu, s, o);
            if (lane >= o) s += t;
        }
        __shared__ int wsum[8];
        if (lane == 31) wsum[w] = s;
        __syncthreads();
        if (w == 0) {
            int t = (lane < 8) ? wsum[lane] : 0;
#pragma unroll
            for (int o = 1; o < 8; o <<= 1) {
                int u = __shfl_up_sync(0xffffffffu, t, o);
                if (lane >= o) t += u;
            }
            if (lane < 8) wsum[lane] = t;
        }
        __syncthreads();
        s_ex[tid] = s - v + ((w > 0) ? wsum[w - 1] : 0);
        __syncthreads();
    }
    int i = blockIdx.x * 256 + tid;
    if (i < NN) {
        int o = g_offp[i] + s_ex[i >> 9];
        g_off[i] = o;
        g_cursor[i] = o;
    }
}

// ================= CSR positional scatter =================
__global__ void k_edge_pos(const int* __restrict__ src, const int* __restrict__ dst) {
    int e = blockIdx.x * blockDim.x + threadIdx.x;
    if (e < NE) {
        int pos = atomicAdd(&g_cursor[dst[e]], 1);
        g_csrc[pos] = src[e];
    }
}

// ========== GEMM1 via HMMA m16n8k16: hs = half(x @ W1), unscaled ==========
// Block: 128 threads (4 warps), 128 rows x 64 cols. Warp: 32 rows (2 M-tiles x 8 N-tiles).
// x staged fp16 in smem [128][136]; W1 transposed fp16 [64][136].
#define XS_STRIDE 136
#define GEMM1_SMEM ((128 * XS_STRIDE + 64 * XS_STRIDE) * 2)   // 52224 B

__global__ void __launch_bounds__(128, 4) k_gemm1(const float* __restrict__ x,
                                                  const float* __restrict__ W1) {
    extern __shared__ __half sh[];
    __half* xs = sh;                       // [128][136]
    __half* wt = sh + 128 * XS_STRIDE;     // [64][136] : wt[n][k]

    const int tid  = threadIdx.x;
    const int warp = tid >> 5;
    const int lane = tid & 31;
    const int g  = lane >> 2;   // 0..7
    const int tg = lane & 3;    // 0..3
    const int row0 = blockIdx.x * 128;

    // W1 [k=128][n=64] -> wt[n][k] fp16
    for (int i = tid; i < 128 * 64; i += 128) {
        int k = i >> 6, n = i & 63;
        wt[n * XS_STRIDE + k] = __float2half(W1[i]);
    }
    // x rows -> xs fp16 (clamped rows for OOB)
    const float4* x4 = reinterpret_cast<const float4*>(x);
    for (int i = tid; i < 128 * 32; i += 128) {
        int r = i >> 5, q = i & 31;
        int grow = min(row0 + r, NN - 1);
        float4 v = x4[(size_t)grow * 32 + q];
        *reinterpret_cast<__half2*>(&xs[r * XS_STRIDE + q * 4]) =
            __float22half2_rn(make_float2(v.x, v.y));
        *reinterpret_cast<__half2*>(&xs[r * XS_STRIDE + q * 4 + 2]) =
            __float22half2_rn(make_float2(v.z, v.w));
    }
    __syncthreads();

    float c[2][8][4];
#pragma unroll
    for (int mt = 0; mt < 2; mt++)
#pragma unroll
        for (int nt = 0; nt < 8; nt++)
#pragma unroll
            for (int p = 0; p < 4; p++) c[mt][nt][p] = 0.0f;

#pragma unroll
    for (int kt = 0; kt < 8; kt++) {
        const int kb = kt * 16;
        unsigned a[2][4], b[8][2];
#pragma unroll
        for (int mt = 0; mt < 2; mt++) {
            int r = warp * 32 + mt * 16 + g;
            const __half* base = &xs[r * XS_STRIDE + kb + tg * 2];
            a[mt][0] = *reinterpret_cast<const unsigned*>(base);
            a[mt][1] = *reinterpret_cast<const unsigned*>(base + 8 * XS_STRIDE);
            a[mt][2] = *reinterpret_cast<const unsigned*>(base + 8);
            a[mt][3] = *reinterpret_cast<const unsigned*>(base + 8 * XS_STRIDE + 8);
        }
#pragma unroll
        for (int nt = 0; nt < 8; nt++) {
            const __half* bb = &wt[(nt * 8 + g) * XS_STRIDE + kb + tg * 2];
            b[nt][0] = *reinterpret_cast<const unsigned*>(bb);
            b[nt][1] = *reinterpret_cast<const unsigned*>(bb + 8);
        }
#pragma unroll
        for (int mt = 0; mt < 2; mt++)
#pragma unroll
            for (int nt = 0; nt < 8; nt++)
                asm volatile(
                    "mma.sync.aligned.m16n8k16.row.col.f32.f16.f16.f32 "
                    "{%0,%1,%2,%3}, {%4,%5,%6,%7}, {%8,%9}, {%0,%1,%2,%3};"
                    : "+f"(c[mt][nt][0]), "+f"(c[mt][nt][1]),
                      "+f"(c[mt][nt][2]), "+f"(c[mt][nt][3])
                    : "r"(a[mt][0]), "r"(a[mt][1]), "r"(a[mt][2]), "r"(a[mt][3]),
                      "r"(b[nt][0]), "r"(b[nt][1]));
    }
    __syncthreads();  // done reading xs; reuse as output staging [128][136]

#pragma unroll
    for (int mt = 0; mt < 2; mt++)
#pragma unroll
        for (int nt = 0; nt < 8; nt++) {
            int r = warp * 32 + mt * 16 + g;
            int col = nt * 8 + tg * 2;
            *reinterpret_cast<__half2*>(&xs[r * XS_STRIDE + col]) =
                __float22half2_rn(make_float2(c[mt][nt][0], c[mt][nt][1]));
            *reinterpret_cast<__half2*>(&xs[(r + 8) * XS_STRIDE + col]) =
                __float22half2_rn(make_float2(c[mt][nt][2], c[mt][nt][3]));
        }
    __syncthreads();

    uint4* hs16 = reinterpret_cast<uint4*>(g_hs);
    for (int i = tid; i < 128 * 8; i += 128) {
        int r = i >> 3, q = i & 7;
        int grow = row0 + r;
        if (grow < NN)
            hs16[(size_t)grow * 8 + q] =
                *reinterpret_cast<uint4*>(&xs[r * XS_STRIDE + q * 8]);
    }
}

// ================= scale: hs[n][:] *= dinv[n]  (on s2, overlapped) ===========
__global__ void __launch_bounds__(256) k_scale() {
    int idx = blockIdx.x * blockDim.x + threadIdx.x;
    if (idx >= NN * 8) return;
    int n = idx >> 3;
    float di = g_dinv[n];
    uint4* hs16 = reinterpret_cast<uint4*>(g_hs);
    uint4 u = hs16[idx];
    unsigned* up = &u.x;
#pragma unroll
    for (int p = 0; p < 4; p++) {
        __half2 h = *reinterpret_cast<__half2*>(&up[p]);
        float2 f = __half22float2(h);
        f.x *= di; f.y *= di;
        up[p] = h2_bits(__float22half2_rn(f));
    }
    hs16[idx] = u;
}

// ===== agg1: warp-per-node, 2x4 edges/iteration, pairwise HADD2 =====
__global__ void __launch_bounds__(256) k_agg1(const float* __restrict__ b1) {
    int wg = (blockIdx.x * blockDim.x + threadIdx.x) >> 5;
    if (wg >= NN) return;
    const int d = wg;
    const int lane = threadIdx.x & 31;
    const int g  = lane >> 3;
    const int fl = lane & 7;

    const uint4* hs4 = reinterpret_cast<const uint4*>(g_hs);

    float facc[8];
#pragma unroll
    for (int p = 0; p < 8; p++) facc[p] = 0.0f;

    const int beg = g_off[d];
    const int cnt = g_indeg[d];
    for (int base = 0; base < cnt; base += 32) {
        int rem = cnt - base;
        int take = rem < 32 ? rem : 32;
        int s = 0;
        if (lane < take) s = __ldg(&g_csrc[beg + base + lane]);
#pragma unroll
        for (int q = 0; q < 32; q += 8) {
            int e0 = q + g;
            int e1 = q + 4 + g;
            int s0 = __shfl_sync(0xffffffffu, s, e0);
            int s1 = __shfl_sync(0xffffffffu, s, e1);
            if (e0 < take) {
                uint4 u0 = __ldg(&hs4[(size_t)s0 * 8 + fl]);
                uint4 u1 = make_uint4(0u, 0u, 0u, 0u);
                if (e1 < take) u1 = __ldg(&hs4[(size_t)s1 * 8 + fl]);
                const __half2* h0 = reinterpret_cast<const __half2*>(&u0);
                const __half2* h1 = reinterpret_cast<const __half2*>(&u1);
#pragma unroll
                for (int p = 0; p < 4; p++) {
                    __half2 hsum = __hadd2(h0[p], h1[p]);
                    float2 f = __half22float2(hsum);
                    facc[2 * p]     += f.x;
                    facc[2 * p + 1] += f.y;
                }
            }
        }
    }

#pragma unroll
    for (int off = 8; off < 32; off <<= 1) {
#pragma unroll
        for (int p = 0; p < 8; p++)
            facc[p] += __shfl_xor_sync(0xffffffffu, facc[p], off);
    }

    if (g == 0) {
        uint4 u = __ldg(&hs4[(size_t)d * 8 + fl]);
        const __half2* hp = reinterpret_cast<const __half2*>(&u);
#pragma unroll
        for (int p = 0; p < 4; p++) {
            float2 f = __half22float2(hp[p]);
            facc[2 * p]     += f.x;
            facc[2 * p + 1] += f.y;
        }
        float di = g_dinv[d];
        const float4* b4 = reinterpret_cast<const float4*>(b1);
        float4 bb0 = b4[fl * 2];
        float4 bb1 = b4[fl * 2 + 1];
        float o0 = fmaxf(fmaf(facc[0], di, bb0.x), 0.0f);
        float o1 = fmaxf(fmaf(facc[1], di, bb0.y), 0.0f);
        float o2 = fmaxf(fmaf(facc[2], di, bb0.z), 0.0f);
        float o3 = fmaxf(fmaf(facc[3], di, bb0.w), 0.0f);
        float o4 = fmaxf(fmaf(facc[4], di, bb1.x), 0.0f);
        float o5 = fmaxf(fmaf(facc[5], di, bb1.y), 0.0f);
        float o6 = fmaxf(fmaf(facc[6], di, bb1.z), 0.0f);
        float o7 = fmaxf(fmaf(facc[7], di, bb1.w), 0.0f);
        uint4 w;
        w.x = h2_bits(__float22half2_rn(make_float2(o0, o1)));
        w.y = h2_bits(__float22half2_rn(make_float2(o2, o3)));
        w.z = h2_bits(__float22half2_rn(make_float2(o4, o5)));
        w.w = h2_bits(__float22half2_rn(make_float2(o6, o7)));
        reinterpret_cast<uint4*>(g_aggh)[(size_t)d * 8 + fl] = w;
    }
}

// ========== GEMM2: h2s = half((aggh @ W2) * dinv[row]) ==========
__global__ void __launch_bounds__(256) k_gemm2(const float* __restrict__ W2) {
    __shared__ float Ws[FH * FO];
    for (int i = threadIdx.x; i < FH * FO; i += blockDim.x) Ws[i] = W2[i];
    __syncthreads();

    int n = blockIdx.x * blockDim.x + threadIdx.x;
    if (n >= NN) return;

    float acc[FO];
#pragma unroll
    for (int j = 0; j < FO; j++) acc[j] = 0.0f;

    const uint4* a4 = reinterpret_cast<const uint4*>(g_aggh) + (size_t)n * 8;
#pragma unroll
    for (int k4 = 0; k4 < 8; k4++) {
        uint4 u = a4[k4];
        const __half2* hp = reinterpret_cast<const __half2*>(&u);
#pragma unroll
        for (int pp = 0; pp < 4; pp++) {
            float2 f = __half22float2(hp[pp]);
            int k = k4 * 8 + pp * 2;
#pragma unroll
            for (int j = 0; j < FO; j++) acc[j] = fmaf(f.x, Ws[k * FO + j], acc[j]);
#pragma unroll
            for (int j = 0; j < FO; j++) acc[j] = fmaf(f.y, Ws[(k + 1) * FO + j], acc[j]);
        }
    }

    float di = g_dinv[n];
    unsigned* o2 = reinterpret_cast<unsigned*>(g_h2s + (size_t)n * 16);
#pragma unroll
    for (int p = 0; p < 5; p++) {
        __half2 h = __float22half2_rn(make_float2(acc[p * 2] * di, acc[p * 2 + 1] * di));
        o2[p] = h2_bits(h);
    }
}

// ===== agg2: warp-per-node, 2x4 edges/iteration, pairwise HADD2 =====
__global__ void __launch_bounds__(256) k_agg2(const float* __restrict__ b2,
                                              float* __restrict__ out) {
    int wg = (blockIdx.x * blockDim.x + threadIdx.x) >> 5;
    if (wg >= NN) return;
    const int d = wg;
    const int lane = threadIdx.x & 31;
    const int g  = lane >> 3;
    const int fl = lane & 7;

    const __half2* h2p = reinterpret_cast<const __half2*>(g_h2s);

    float2 acc = make_float2(0.f, 0.f);

    const int beg = g_off[d];
    const int cnt = g_indeg[d];
    for (int base = 0; base < cnt; base += 32) {
        int rem = cnt - base;
        int take = rem < 32 ? rem : 32;
        int s = 0;
        if (lane < take) s = __ldg(&g_csrc[beg + base + lane]);
#pragma unroll
        for (int q = 0; q < 32; q += 8) {
            int e0 = q + g;
            int e1 = q + 4 + g;
            int s0 = __shfl_sync(0xffffffffu, s, e0);
            int s1 = __shfl_sync(0xffffffffu, s, e1);
            if (e0 < take && fl < 5) {
                __half2 v0 = __ldg(&h2p[(size_t)s0 * 8 + fl]);
                __half2 v1 = __float2half2_rn(0.0f);
                if (e1 < take) v1 = __ldg(&h2p[(size_t)s1 * 8 + fl]);
                float2 f = __half22float2(__hadd2(v0, v1));
                acc.x += f.x;
                acc.y += f.y;
            }
        }
    }

#pragma unroll
    for (int off = 8; off < 32; off <<= 1) {
        acc.x += __shfl_xor_sync(0xffffffffu, acc.x, off);
        acc.y += __shfl_xor_sync(0xffffffffu, acc.y, off);
    }

    if (g == 0 && fl < 5) {
        float2 self = __half22float2(__ldg(&h2p[(size_t)d * 8 + fl]));
        acc.x += self.x;
        acc.y += self.y;
        float di = g_dinv[d];
        float* op = out + (size_t)d * FO;
        op[fl * 2]     = fmaf(acc.x, di, b2[fl * 2]);
        op[fl * 2 + 1] = fmaf(acc.y, di, b2[fl * 2 + 1]);
    }
}

extern "C" void kernel_launch(void* const* d_in, const int* in_sizes, int n_in,
                              void* d_out, int out_size) {
    const float* x  = (const float*)d_in[0];
    const int*   ei = (const int*)d_in[1];
    const float* W1 = (const float*)d_in[2];
    const float* b1 = (const float*)d_in[3];
    const float* W2 = (const float*)d_in[4];
    const float* b2 = (const float*)d_in[5];
    float* out = (float*)d_out;

    const int* src = ei;
    const int* dst = ei + NE;

    static bool init_done = false;
    static cudaStream_t s2;
    static cudaEvent_t ev_fork, ev_scan1, ev_join;
    static void* indeg_ptr = nullptr;
    if (!init_done) {
        cudaFuncSetAttribute(k_gemm1, cudaFuncAttributeMaxDynamicSharedMemorySize,
                             GEMM1_SMEM);
        cudaStreamCreateWithFlags(&s2, cudaStreamNonBlocking);
        cudaEventCreateWithFlags(&ev_fork, cudaEventDisableTiming);
        cudaEventCreateWithFlags(&ev_scan1, cudaEventDisableTiming);
        cudaEventCreateWithFlags(&ev_join, cudaEventDisableTiming);
        cudaGetSymbolAddress(&indeg_ptr, g_indeg);
        init_done = true;
    }

    // ---- fork immediately: gemm1 has no input deps ----
    cudaEventRecord(ev_fork, 0);
    cudaStreamWaitEvent(s2, ev_fork, 0);
    k_gemm1<<<(NN + 127) / 128, 128, GEMM1_SMEM, s2>>>(x, W1);

    // ---- prepass on capture stream, concurrent with gemm1 ----
    cudaMemsetAsync(indeg_ptr, 0, NN * sizeof(int), 0);
    k_indeg<<<(NE + 255) / 256, 256>>>(dst);
    k_scan1<<<NSCAN, SCAN_BLK>>>();
    cudaEventRecord(ev_scan1, 0);

    // s2: scale hs as soon as gemm1 + scan1 are both done
    cudaStreamWaitEvent(s2, ev_scan1, 0);
    k_scale<<<(NN * 8 + 255) / 256, 256, 0, s2>>>();

    k_scan_apply<<<(NN + 255) / 256, 256>>>();
    k_edge_pos<<<(NE + 255) / 256, 256>>>(src, dst);

    // ---- join ----
    cudaEventRecord(ev_join, s2);
    cudaStreamWaitEvent(0, ev_join, 0);

    k_agg1<<<(NN * 32 + 255) / 256, 256>>>(b1);
    k_gemm2<<<(NN + 255) / 256, 256>>>(W2);
    k_agg2<<<(NN * 32 + 255) / 256, 256>>>(b2, out);
}

// round 16
// speedup vs baseline: 1.2958x; 1.1293x over previous
#include <cuda_runtime.h>
#include <cuda_fp16.h>

#define NN 100000
#define NE 1600000
#define FIN 128
#define FH  64
#define FO  10

#define SCAN_BLK 512
#define NSCAN ((NN + SCAN_BLK - 1) / SCAN_BLK)   // 196

typedef unsigned long long u64;

// ---- scratch (device globals; no allocation allowed) ----
__device__ int   g_indeg[NN];
__device__ int   g_off[NN];
__device__ int   g_cursor[NN];
__device__ int   g_offp[NN];
__device__ int   g_bsum[NSCAN];
__device__ int   g_csrc[NE];
__device__ float g_dinv[NN];
__device__ __align__(16) __half g_hs[NN * FH];    // x@W1 (unscaled, then *= dinv)
__device__ __align__(16) __half g_aggh[NN * FH];  // fp16 relu(b1+dinv*(...)), 128B rows
__device__ __align__(16) __half g_h2s[NN * 16];   // (agg@W2)*dinv, fp16, stride 16

__device__ __forceinline__ unsigned h2_bits(__half2 h) {
    return *reinterpret_cast<unsigned*>(&h);
}

// ================= degree =================
__global__ void k_indeg(const int* __restrict__ dst) {
    int e = blockIdx.x * blockDim.x + threadIdx.x;
    if (e < NE) atomicAdd(&g_indeg[dst[e]], 1);
}

// ================= scan pass 1 (+ dinv fused) =================
__global__ void __launch_bounds__(SCAN_BLK) k_scan1() {
    int i = blockIdx.x * SCAN_BLK + threadIdx.x;
    int v = (i < NN) ? g_indeg[i] : 0;
    if (i < NN) g_dinv[i] = rsqrtf(1.0f + (float)v);
    int lane = threadIdx.x & 31, w = threadIdx.x >> 5;
    int s = v;
#pragma unroll
    for (int o = 1; o < 32; o <<= 1) {
        int t = __shfl_up_sync(0xffffffffu, s, o);
        if (lane >= o) s += t;
    }
    __shared__ int wsum[16];
    if (lane == 31) wsum[w] = s;
    __syncthreads();
    if (w == 0) {
        int t = (lane < 16) ? wsum[lane] : 0;
#pragma unroll
        for (int o = 1; o < 16; o <<= 1) {
            int u = __shfl_up_sync(0xffffffffu, t, o);
            if (lane >= o) t += u;
        }
        if (lane < 16) wsum[lane] = t;
    }
    __syncthreads();
    int excl = s - v + ((w > 0) ? wsum[w - 1] : 0);
    if (i < NN) g_offp[i] = excl;
    if (threadIdx.x == 0) g_bsum[blockIdx.x] = wsum[15];
}

// ===== scan pass 2 fused into apply =====
__global__ void __launch_bounds__(256) k_scan_apply() {
    __shared__ int s_ex[256];
    int tid = threadIdx.x;
    {
        int v = (tid < NSCAN) ? g_bsum[tid] : 0;
        int lane = tid & 31, w = tid >> 5;
        int s = v;
#pragma unroll
        for (int o = 1; o < 32; o <<= 1) {
            int t = __shfl_up_sync(0xffffffffu, s, o);
            if (lane >= o) s += t;
        }
        __shared__ int wsum[8];
        if (lane == 31) wsum[w] = s;
        __syncthreads();
        if (w == 0) {
            int t = (lane < 8) ? wsum[lane] : 0;
#pragma unroll
            for (int o = 1; o < 8; o <<= 1) {
                int u = __shfl_up_sync(0xffffffffu, t, o);
                if (lane >= o) t += u;
            }
            if (lane < 8) wsum[lane] = t;
        }
        __syncthreads();
        s_ex[tid] = s - v + ((w > 0) ? wsum[w - 1] : 0);
        __syncthreads();
    }
    int i = blockIdx.x * 256 + tid;
    if (i < NN) {
        int o = g_offp[i] + s_ex[i >> 9];
        g_off[i] = o;
        g_cursor[i] = o;
    }
}

// ================= CSR positional scatter =================
__global__ void k_edge_pos(const int* __restrict__ src, const int* __restrict__ dst) {
    int e = blockIdx.x * blockDim.x + threadIdx.x;
    if (e < NE) {
        int pos = atomicAdd(&g_cursor[dst[e]], 1);
        g_csrc[pos] = src[e];
    }
}

// ========== GEMM1 via HMMA m16n8k16: hs = half(x @ W1), unscaled ==========
#define XS_STRIDE 136
#define GEMM1_SMEM ((128 * XS_STRIDE + 64 * XS_STRIDE) * 2)   // 52224 B

__global__ void __launch_bounds__(128, 4) k_gemm1(const float* __restrict__ x,
                                                  const float* __restrict__ W1) {
    extern __shared__ __half sh[];
    __half* xs = sh;                       // [128][136]
    __half* wt = sh + 128 * XS_STRIDE;     // [64][136] : wt[n][k]

    const int tid  = threadIdx.x;
    const int warp = tid >> 5;
    const int lane = tid & 31;
    const int g  = lane >> 2;
    const int tg = lane & 3;
    const int row0 = blockIdx.x * 128;

    for (int i = tid; i < 128 * 64; i += 128) {
        int k = i >> 6, n = i & 63;
        wt[n * XS_STRIDE + k] = __float2half(W1[i]);
    }
    const float4* x4 = reinterpret_cast<const float4*>(x);
    for (int i = tid; i < 128 * 32; i += 128) {
        int r = i >> 5, q = i & 31;
        int grow = min(row0 + r, NN - 1);
        float4 v = x4[(size_t)grow * 32 + q];
        *reinterpret_cast<__half2*>(&xs[r * XS_STRIDE + q * 4]) =
            __float22half2_rn(make_float2(v.x, v.y));
        *reinterpret_cast<__half2*>(&xs[r * XS_STRIDE + q * 4 + 2]) =
            __float22half2_rn(make_float2(v.z, v.w));
    }
    __syncthreads();

    float c[2][8][4];
#pragma unroll
    for (int mt = 0; mt < 2; mt++)
#pragma unroll
        for (int nt = 0; nt < 8; nt++)
#pragma unroll
            for (int p = 0; p < 4; p++) c[mt][nt][p] = 0.0f;

#pragma unroll
    for (int kt = 0; kt < 8; kt++) {
        const int kb = kt * 16;
        unsigned a[2][4], b[8][2];
#pragma unroll
        for (int mt = 0; mt < 2; mt++) {
            int r = warp * 32 + mt * 16 + g;
            const __half* base = &xs[r * XS_STRIDE + kb + tg * 2];
            a[mt][0] = *reinterpret_cast<const unsigned*>(base);
            a[mt][1] = *reinterpret_cast<const unsigned*>(base + 8 * XS_STRIDE);
            a[mt][2] = *reinterpret_cast<const unsigned*>(base + 8);
            a[mt][3] = *reinterpret_cast<const unsigned*>(base + 8 * XS_STRIDE + 8);
        }
#pragma unroll
        for (int nt = 0; nt < 8; nt++) {
            const __half* bb = &wt[(nt * 8 + g) * XS_STRIDE + kb + tg * 2];
            b[nt][0] = *reinterpret_cast<const unsigned*>(bb);
            b[nt][1] = *reinterpret_cast<const unsigned*>(bb + 8);
        }
#pragma unroll
        for (int mt = 0; mt < 2; mt++)
#pragma unroll
            for (int nt = 0; nt < 8; nt++)
                asm volatile(
                    "mma.sync.aligned.m16n8k16.row.col.f32.f16.f16.f32 "
                    "{%0,%1,%2,%3}, {%4,%5,%6,%7}, {%8,%9}, {%0,%1,%2,%3};"
                    : "+f"(c[mt][nt][0]), "+f"(c[mt][nt][1]),
                      "+f"(c[mt][nt][2]), "+f"(c[mt][nt][3])
                    : "r"(a[mt][0]), "r"(a[mt][1]), "r"(a[mt][2]), "r"(a[mt][3]),
                      "r"(b[nt][0]), "r"(b[nt][1]));
    }
    __syncthreads();

#pragma unroll
    for (int mt = 0; mt < 2; mt++)
#pragma unroll
        for (int nt = 0; nt < 8; nt++) {
            int r = warp * 32 + mt * 16 + g;
            int col = nt * 8 + tg * 2;
            *reinterpret_cast<__half2*>(&xs[r * XS_STRIDE + col]) =
                __float22half2_rn(make_float2(c[mt][nt][0], c[mt][nt][1]));
            *reinterpret_cast<__half2*>(&xs[(r + 8) * XS_STRIDE + col]) =
                __float22half2_rn(make_float2(c[mt][nt][2], c[mt][nt][3]));
        }
    __syncthreads();

    uint4* hs16 = reinterpret_cast<uint4*>(g_hs);
    for (int i = tid; i < 128 * 8; i += 128) {
        int r = i >> 3, q = i & 7;
        int grow = row0 + r;
        if (grow < NN)
            hs16[(size_t)grow * 8 + q] =
                *reinterpret_cast<uint4*>(&xs[r * XS_STRIDE + q * 8]);
    }
}

// ================= scale: hs[n][:] *= dinv[n]  (on s2, overlapped) ===========
__global__ void __launch_bounds__(256) k_scale() {
    int idx = blockIdx.x * blockDim.x + threadIdx.x;
    if (idx >= NN * 8) return;
    int n = idx >> 3;
    float di = g_dinv[n];
    uint4* hs16 = reinterpret_cast<uint4*>(g_hs);
    uint4 u = hs16[idx];
    unsigned* up = &u.x;
#pragma unroll
    for (int p = 0; p < 4; p++) {
        __half2 h = *reinterpret_cast<__half2*>(&up[p]);
        float2 f = __half22float2(h);
        f.x *= di; f.y *= di;
        up[p] = h2_bits(__float22half2_rn(f));
    }
    hs16[idx] = u;
}

// ===== agg1: 2 nodes/warp (16 lanes each: 2 edge-groups x 8 feature-lanes) =====
__global__ void __launch_bounds__(256) k_agg1(const float* __restrict__ b1) {
    int warp_id = (blockIdx.x * blockDim.x + threadIdx.x) >> 5;
    const int lane = threadIdx.x & 31;
    const int half = lane >> 4;   // node within warp
    const int hl = lane & 15;
    const int g  = hl >> 3;       // edge group 0..1
    const int fl = hl & 7;        // feature chunk
    const int slbase = half << 4; // shfl source-lane base

    int d = warp_id * 2 + half;
    const bool valid = d < NN;
    if (!valid) d = NN - 1;       // clamp; writes suppressed

    const uint4* hs4 = reinterpret_cast<const uint4*>(g_hs);

    float facc[8];
#pragma unroll
    for (int p = 0; p < 8; p++) facc[p] = 0.0f;

    const int beg = g_off[d];
    const int cnt = valid ? g_indeg[d] : 0;
    const int cnt_other = __shfl_xor_sync(0xffffffffu, cnt, 16);
    const int cntmax = cnt > cnt_other ? cnt : cnt_other;

    for (int base = 0; base < cntmax; base += 16) {
        int rem = cnt - base;
        int take = rem < 16 ? rem : 16;   // may be <= 0 for this half
        int s = 0;
        if (hl < take) s = __ldg(&g_csrc[beg + base + hl]);
#pragma unroll
        for (int q = 0; q < 16; q += 4) {
            int e0 = q + g;
            int e1 = q + 2 + g;
            int s0 = __shfl_sync(0xffffffffu, s, slbase + e0);
            int s1 = __shfl_sync(0xffffffffu, s, slbase + e1);
            if (e0 < take) {
                uint4 u0 = __ldg(&hs4[(size_t)s0 * 8 + fl]);
                uint4 u1 = make_uint4(0u, 0u, 0u, 0u);
                if (e1 < take) u1 = __ldg(&hs4[(size_t)s1 * 8 + fl]);
                const __half2* h0 = reinterpret_cast<const __half2*>(&u0);
                const __half2* h1 = reinterpret_cast<const __half2*>(&u1);
#pragma unroll
                for (int p = 0; p < 4; p++) {
                    __half2 hsum = __hadd2(h0[p], h1[p]);
                    float2 f = __half22float2(hsum);
                    facc[2 * p]     += f.x;
                    facc[2 * p + 1] += f.y;
                }
            }
        }
    }

    // reduce across the 2 edge groups within each half (lanes differing in bit 3)
#pragma unroll
    for (int p = 0; p < 8; p++)
        facc[p] += __shfl_xor_sync(0xffffffffu, facc[p], 8);

    if (g == 0 && valid) {
        uint4 u = __ldg(&hs4[(size_t)d * 8 + fl]);
        const __half2* hp = reinterpret_cast<const __half2*>(&u);
#pragma unroll
        for (int p = 0; p < 4; p++) {
            float2 f = __half22float2(hp[p]);
            facc[2 * p]     += f.x;
            facc[2 * p + 1] += f.y;
        }
        float di = g_dinv[d];
        const float4* b4 = reinterpret_cast<const float4*>(b1);
        float4 bb0 = b4[fl * 2];
        float4 bb1 = b4[fl * 2 + 1];
        float o0 = fmaxf(fmaf(facc[0], di, bb0.x), 0.0f);
        float o1 = fmaxf(fmaf(facc[1], di, bb0.y), 0.0f);
        float o2 = fmaxf(fmaf(facc[2], di, bb0.z), 0.0f);
        float o3 = fmaxf(fmaf(facc[3], di, bb0.w), 0.0f);
        float o4 = fmaxf(fmaf(facc[4], di, bb1.x), 0.0f);
        float o5 = fmaxf(fmaf(facc[5], di, bb1.y), 0.0f);
        float o6 = fmaxf(fmaf(facc[6], di, bb1.z), 0.0f);
        float o7 = fmaxf(fmaf(facc[7], di, bb1.w), 0.0f);
        uint4 w;
        w.x = h2_bits(__float22half2_rn(make_float2(o0, o1)));
        w.y = h2_bits(__float22half2_rn(make_float2(o2, o3)));
        w.z = h2_bits(__float22half2_rn(make_float2(o4, o5)));
        w.w = h2_bits(__float22half2_rn(make_float2(o6, o7)));
        reinterpret_cast<uint4*>(g_aggh)[(size_t)d * 8 + fl] = w;
    }
}

// ========== GEMM2: h2s = half((aggh @ W2) * dinv[row]) ==========
__global__ void __launch_bounds__(256) k_gemm2(const float* __restrict__ W2) {
    __shared__ float Ws[FH * FO];
    for (int i = threadIdx.x; i < FH * FO; i += blockDim.x) Ws[i] = W2[i];
    __syncthreads();

    int n = blockIdx.x * blockDim.x + threadIdx.x;
    if (n >= NN) return;

    float acc[FO];
#pragma unroll
    for (int j = 0; j < FO; j++) acc[j] = 0.0f;

    const uint4* a4 = reinterpret_cast<const uint4*>(g_aggh) + (size_t)n * 8;
#pragma unroll
    for (int k4 = 0; k4 < 8; k4++) {
        uint4 u = a4[k4];
        const __half2* hp = reinterpret_cast<const __half2*>(&u);
#pragma unroll
        for (int pp = 0; pp < 4; pp++) {
            float2 f = __half22float2(hp[pp]);
            int k = k4 * 8 + pp * 2;
#pragma unroll
            for (int j = 0; j < FO; j++) acc[j] = fmaf(f.x, Ws[k * FO + j], acc[j]);
#pragma unroll
            for (int j = 0; j < FO; j++) acc[j] = fmaf(f.y, Ws[(k + 1) * FO + j], acc[j]);
        }
    }

    float di = g_dinv[n];
    unsigned* o2 = reinterpret_cast<unsigned*>(g_h2s + (size_t)n * 16);
#pragma unroll
    for (int p = 0; p < 5; p++) {
        __half2 h = __float22half2_rn(make_float2(acc[p * 2] * di, acc[p * 2 + 1] * di));
        o2[p] = h2_bits(h);
    }
}

// ===== agg2: 2 nodes/warp (16 lanes each: 2 edge-groups x 8 feature-lanes) =====
__global__ void __launch_bounds__(256) k_agg2(const float* __restrict__ b2,
                                              float* __restrict__ out) {
    int warp_id = (blockIdx.x * blockDim.x + threadIdx.x) >> 5;
    const int lane = threadIdx.x & 31;
    const int half = lane >> 4;
    const int hl = lane & 15;
    const int g  = hl >> 3;
    const int fl = hl & 7;
    const int slbase = half << 4;

    int d = warp_id * 2 + half;
    const bool valid = d < NN;
    if (!valid) d = NN - 1;

    const __half2* h2p = reinterpret_cast<const __half2*>(g_h2s);

    float2 acc = make_float2(0.f, 0.f);

    const int beg = g_off[d];
    const int cnt = valid ? g_indeg[d] : 0;
    const int cnt_other = __shfl_xor_sync(0xffffffffu, cnt, 16);
    const int cntmax = cnt > cnt_other ? cnt : cnt_other;

    for (int base = 0; base < cntmax; base += 16) {
        int rem = cnt - base;
        int take = rem < 16 ? rem : 16;
        int s = 0;
        if (hl < take) s = __ldg(&g_csrc[beg + base + hl]);
#pragma unroll
        for (int q = 0; q < 16; q += 4) {
            int e0 = q + g;
            int e1 = q + 2 + g;
            int s0 = __shfl_sync(0xffffffffu, s, slbase + e0);
            int s1 = __shfl_sync(0xffffffffu, s, slbase + e1);
            if (e0 < take && fl < 5) {
                __half2 v0 = __ldg(&h2p[(size_t)s0 * 8 + fl]);
                __half2 v1 = __float2half2_rn(0.0f);
                if (e1 < take) v1 = __ldg(&h2p[(size_t)s1 * 8 + fl]);
                float2 f = __half22float2(__hadd2(v0, v1));
                acc.x += f.x;
                acc.y += f.y;
            }
        }
    }

    // reduce across the 2 edge groups within each half
    acc.x += __shfl_xor_sync(0xffffffffu, acc.x, 8);
    acc.y += __shfl_xor_sync(0xffffffffu, acc.y, 8);

    if (g == 0 && fl < 5 && valid) {
        float2 self = __half22float2(__ldg(&h2p[(size_t)d * 8 + fl]));
        acc.x += self.x;
        acc.y += self.y;
        float di = g_dinv[d];
        float* op = out + (size_t)d * FO;
        op[fl * 2]     = fmaf(acc.x, di, b2[fl * 2]);
        op[fl * 2 + 1] = fmaf(acc.y, di, b2[fl * 2 + 1]);
    }
}

extern "C" void kernel_launch(void* const* d_in, const int* in_sizes, int n_in,
                              void* d_out, int out_size) {
    const float* x  = (const float*)d_in[0];
    const int*   ei = (const int*)d_in[1];
    const float* W1 = (const float*)d_in[2];
    const float* b1 = (const float*)d_in[3];
    const float* W2 = (const float*)d_in[4];
    const float* b2 = (const float*)d_in[5];
    float* out = (float*)d_out;

    const int* src = ei;
    const int* dst = ei + NE;

    static bool init_done = false;
    static cudaStream_t s2;
    static cudaEvent_t ev_fork, ev_scan1, ev_join;
    static void* indeg_ptr = nullptr;
    if (!init_done) {
        cudaFuncSetAttribute(k_gemm1, cudaFuncAttributeMaxDynamicSharedMemorySize,
                             GEMM1_SMEM);
        cudaStreamCreateWithFlags(&s2, cudaStreamNonBlocking);
        cudaEventCreateWithFlags(&ev_fork, cudaEventDisableTiming);
        cudaEventCreateWithFlags(&ev_scan1, cudaEventDisableTiming);
        cudaEventCreateWithFlags(&ev_join, cudaEventDisableTiming);
        cudaGetSymbolAddress(&indeg_ptr, g_indeg);
        init_done = true;
    }

    // ---- fork immediately: gemm1 has no input deps ----
    cudaEventRecord(ev_fork, 0);
    cudaStreamWaitEvent(s2, ev_fork, 0);
    k_gemm1<<<(NN + 127) / 128, 128, GEMM1_SMEM, s2>>>(x, W1);

    // ---- prepass on capture stream, concurrent with gemm1 ----
    cudaMemsetAsync(indeg_ptr, 0, NN * sizeof(int), 0);
    k_indeg<<<(NE + 255) / 256, 256>>>(dst);
    k_scan1<<<NSCAN, SCAN_BLK>>>();
    cudaEventRecord(ev_scan1, 0);

    // s2: scale hs as soon as gemm1 + scan1 are both done
    cudaStreamWaitEvent(s2, ev_scan1, 0);
    k_scale<<<(NN * 8 + 255) / 256, 256, 0, s2>>>();

    k_scan_apply<<<(NN + 255) / 256, 256>>>();
    k_edge_pos<<<(NE + 255) / 256, 256>>>(src, dst);

    // ---- join ----
    cudaEventRecord(ev_join, s2);
    cudaStreamWaitEvent(0, ev_join, 0);

    // 2 nodes per warp: 16 nodes per 256-thread block
    k_agg1<<<(NN + 15) / 16, 256>>>(b1);
    k_gemm2<<<(NN + 255) / 256, 256>>>(W2);
    k_agg2<<<(NN + 15) / 16, 256>>>(b2, out);
}